// round 15
// baseline (speedup 1.0000x reference)
#include <cuda_runtime.h>
#include <cuda_fp16.h>
#include <cstdint>
#include <cstddef>

extern "C" __device__ float __nv_logf(float);

#define B_  8192
#define LD_ 512
#define V_  100
#define E_  256
#define H_  256
#define G_  1024   // 4*H
#define T_  100

// A-fragment buffer: [mtile(512)][ktile(32)][lane(32)][reg(4)] uint32 (fp16x2)
#define AFW (512 * 32 * 32 * 4)
// B-fragment buffers: [ntile(128)][ktile(KT)][lane(32)][reg(2)] uint32
#define B0W (128 * 16 * 32 * 2)
#define B1W (128 * 32 * 32 * 2)

// ------------------------- device scratch ----------------------------------
__device__ unsigned g_AH[2 * AFW];     // hi limb, ping-pong
__device__ unsigned g_AM[2 * AFW];     // mid limb, ping-pong
__device__ unsigned g_B0[2 * B0W];     // 2 limbs concatenated
__device__ unsigned g_B1[2 * B1W];
__device__ float g_latbase[B_ * G_];   // [row][j*4+g]  (unit-major p2 layout)
__device__ float g_embtab [V_ * G_];   // [v][j*4+g]
__device__ float g_lath   [B_ * E_];
__device__ float g_h1f    [B_ * H_];   // fp32 h1 for logits
__device__ float g_c0     [B_ * H_];
__device__ float g_c1     [B_ * H_];
__device__ float g_Wih0latt[E_ * G_];
__device__ float g_Wlpt   [LD_ * E_];
__device__ float g_Woutt  [H_ * V_];
__device__ float g_bias01 [G_];        // p2 layout
__device__ float g_bias1p [G_];        // p2 layout
__device__ int   g_tok    [B_];
__device__ uint2 g_keys   [T_];

// ------------------------- XLA-matching elementwise math -------------------
__device__ __forceinline__ float tanh_xla(float x) {
    float ax = fabsf(x);
    float xc = fminf(fmaxf(x, -7.99881172180175781f), 7.99881172180175781f);
    float x2 = xc * xc;
    float nm = -2.76076847742355e-16f;
    nm = fmaf(x2, nm,  2.00018790482477e-13f);
    nm = fmaf(x2, nm, -8.60467152213735e-11f);
    nm = fmaf(x2, nm,  5.12229709037114e-08f);
    nm = fmaf(x2, nm,  1.48572235717979e-05f);
    nm = fmaf(x2, nm,  6.37261928875436e-04f);
    nm = fmaf(x2, nm,  4.89352455891786e-03f);
    nm = xc * nm;
    float dn = 1.19825839466702e-06f;
    dn = fmaf(x2, dn,  1.18534705686654e-04f);
    dn = fmaf(x2, dn,  2.26843463243900e-03f);
    dn = fmaf(x2, dn,  4.89352518554385e-03f);
    return (ax < 0.0004f) ? x : (nm / dn);
}
__device__ __forceinline__ float sigmoid_xla(float x) {
    return 0.5f * tanh_xla(0.5f * x) + 0.5f;
}
// 2-limb fp16 split: a = h + m + l, |l| <= 2^-22 |a| (approx)
__device__ __forceinline__ void split2(float a, __half& h, __half& m) {
    h = __float2half_rn(a);
    m = __float2half_rn(a - __half2float(h));
}

// ------------------------- threefry2x32 ------------------------------------
__device__ __forceinline__ void tf2x32(uint32_t k0, uint32_t k1,
                                       uint32_t x0, uint32_t x1,
                                       uint32_t& o0, uint32_t& o1) {
    uint32_t k2 = k0 ^ k1 ^ 0x1BD11BDAu;
    x0 += k0; x1 += k1;
#define TFR4(a,b,c,d) \
    x0 += x1; x1 = (x1 << a) | (x1 >> (32 - a)); x1 ^= x0; \
    x0 += x1; x1 = (x1 << b) | (x1 >> (32 - b)); x1 ^= x0; \
    x0 += x1; x1 = (x1 << c) | (x1 >> (32 - c)); x1 ^= x0; \
    x0 += x1; x1 = (x1 << d) | (x1 >> (32 - d)); x1 ^= x0;
    TFR4(13,15,26,6)  x0 += k1; x1 += k2 + 1u;
    TFR4(17,29,16,24) x0 += k2; x1 += k0 + 2u;
    TFR4(13,15,26,6)  x0 += k0; x1 += k1 + 3u;
    TFR4(17,29,16,24) x0 += k1; x1 += k2 + 4u;
    TFR4(13,15,26,6)  x0 += k2; x1 += k0 + 5u;
#undef TFR4
    o0 = x0; o1 = x1;
}

// ------------------------- HMMA m16n8k16 fp16 ------------------------------
__device__ __forceinline__ void mma16816(float* d, const uint4& a, const uint2& b) {
    asm volatile("mma.sync.aligned.m16n8k16.row.col.f32.f16.f16.f32 "
        "{%0,%1,%2,%3}, {%4,%5,%6,%7}, {%8,%9}, {%0,%1,%2,%3};"
        : "+f"(d[0]), "+f"(d[1]), "+f"(d[2]), "+f"(d[3])
        : "r"(a.x), "r"(a.y), "r"(a.z), "r"(a.w), "r"(b.x), "r"(b.y));
}

// ------------------------- fused setup kernel ------------------------------
// One kernel for all packing/init so the ncu skip-window lands on loop kernels.
// p2 permutation: original gate col n = g*256 + j  ->  p2 = j*4 + g
// B-frag slot: nt=p>>3, lane=(p&7)*4+((k&7)>>1), reg=(k>>3)&1, half=k&1, kt=k>>4.
__global__ void setup_kernel(const float* __restrict__ Wih0, const float* __restrict__ Wlp,
                             const float* __restrict__ Wout,
                             const float* __restrict__ bih0, const float* __restrict__ bhh0,
                             const float* __restrict__ bih1, const float* __restrict__ bhh1,
                             const float* __restrict__ Whh0, const float* __restrict__ Wih1,
                             const float* __restrict__ Whh1, const float* __restrict__ emb) {
    int i = blockIdx.x * blockDim.x + threadIdx.x;
    if (i < G_ * H_) {                 // i = n*256 + k
        int n = i >> 8, k = i & 255;
        int p = (n & 255) * 4 + (n >> 8);
        g_Wih0latt[k * G_ + p] = Wih0[n * 512 + 256 + k];
    }
    if (i < E_ * LD_) {
        int n = i >> 9, k = i & 511;
        g_Wlpt[k * E_ + n] = Wlp[i];
    }
    if (i < V_ * H_) {
        int v = i >> 8, k = i & 255;
        g_Woutt[k * V_ + v] = Wout[i];
    }
    if (i < G_) {
        int p = (i & 255) * 4 + (i >> 8);
        g_bias01[p] = bih0[i] + bhh0[i];
        g_bias1p[p] = bih1[i] + bhh1[i];
    }
    if (i < G_ * 512) {                  // B1 frags: layer 1, K = 512
        int n = i >> 9, k = i & 511;
        float wv = (k < 256) ? Wih1[n * 256 + k] : Whh1[n * 256 + k - 256];
        int g = n >> 8, j = n & 255;
        int p = (j >> 3) * 32 + g * 8 + (j & 7);
        int nt = p >> 3;
        int lanei = (p & 7) * 4 + ((k & 7) >> 1);
        int reg = (k >> 3) & 1, half = k & 1, kt = k >> 4;
        size_t idx = ((((size_t)nt * 32 + kt) * 32 + lanei) * 2 + reg) * 2 + half;
        __half hh, mm; split2(wv, hh, mm);
        __half* b = reinterpret_cast<__half*>(g_B1);
        b[idx] = hh; b[(size_t)2 * B1W + idx] = mm;
    }
    if (i < G_ * 256) {                  // B0 frags: layer 0, K = 256
        int n = i >> 8, k = i & 255;
        float wv = Whh0[i];
        int g = n >> 8, j = n & 255;
        int p = (j >> 3) * 32 + g * 8 + (j & 7);
        int nt = p >> 3;
        int lanei = (p & 7) * 4 + ((k & 7) >> 1);
        int reg = (k >> 3) & 1, half = k & 1, kt = k >> 4;
        size_t idx = ((((size_t)nt * 16 + kt) * 32 + lanei) * 2 + reg) * 2 + half;
        __half hh, mm; split2(wv, hh, mm);
        __half* b = reinterpret_cast<__half*>(g_B0);
        b[idx] = hh; b[(size_t)2 * B0W + idx] = mm;
    }
    if (i < V_ * 1024) {                 // embtab: 100x1024 dot products, K=256
        int v = i >> 10, p = i & 1023;
        int n = (p & 3) * 256 + (p >> 2);
        const float* er = emb + v * E_;
        const float* wr = Wih0 + n * 512;
        float s = 0.f;
        for (int k = 0; k < 256; ++k) s = fmaf(er[k], wr[k], s);
        g_embtab[v * G_ + p] = s;
    }
    if (i < AFW / 4) {    // zero ping buffer (buffer 0) of A-frag limbs
        ((uint4*)g_AH)[i] = make_uint4(0, 0, 0, 0);
        ((uint4*)g_AM)[i] = make_uint4(0, 0, 0, 0);
    }
    if (i < B_ * H_) { g_c0[i] = 0.0f; g_c1[i] = 0.0f; }
    if (i < B_) g_tok[i] = 1;                       // START_TOKEN
    if (i < T_) {
        uint32_t o0, o1;
        tf2x32(0u, 42u, 0u, (uint32_t)i, o0, o1);   // partitionable split
        g_keys[i] = make_uint2(o0, o1);
    }
}

// ------------------------- fp32 precompute GEMM (outside loop) --------------
__global__ __launch_bounds__(256, 2)
void sgemm0(const float* __restrict__ A, int lda, const float* __restrict__ Wt,
            const float* __restrict__ bias, float* __restrict__ C, int M, int N, int K) {
    const int bm = blockIdx.y * 128, bn = blockIdx.x * 128;
    const int tid = threadIdx.x, tx = tid & 15, ty = tid >> 4;
    __shared__ float As[2][16][128];
    __shared__ float Bs[2][16][128];
    float acc[8][8] = {};
    const int arow = tid >> 2, ak = (tid & 3) * 4;
    const int brow = tid >> 5, bcol = (tid & 31) * 4;
    const int r0 = min(bm + arow, M - 1);
    const int r1 = min(bm + 64 + arow, M - 1);
    float4 ra0 = *(const float4*)(A + (size_t)r0 * lda + ak);
    float4 ra1 = *(const float4*)(A + (size_t)r1 * lda + ak);
    float4 rb0 = *(const float4*)(Wt + (size_t)brow * N + bn + bcol);
    float4 rb1 = *(const float4*)(Wt + (size_t)(brow + 8) * N + bn + bcol);
    int buf = 0;
    As[0][ak+0][arow]=ra0.x; As[0][ak+1][arow]=ra0.y; As[0][ak+2][arow]=ra0.z; As[0][ak+3][arow]=ra0.w;
    As[0][ak+0][64+arow]=ra1.x; As[0][ak+1][64+arow]=ra1.y; As[0][ak+2][64+arow]=ra1.z; As[0][ak+3][64+arow]=ra1.w;
    *(float4*)&Bs[0][brow][bcol] = rb0; *(float4*)&Bs[0][brow+8][bcol] = rb1;
    __syncthreads();
    const int ktiles = K >> 4;
    for (int t = 0; t < ktiles; ++t) {
        if (t + 1 < ktiles) {
            int ko = (t + 1) * 16;
            ra0 = *(const float4*)(A + (size_t)r0 * lda + ko + ak);
            ra1 = *(const float4*)(A + (size_t)r1 * lda + ko + ak);
            rb0 = *(const float4*)(Wt + (size_t)(ko + brow) * N + bn + bcol);
            rb1 = *(const float4*)(Wt + (size_t)(ko + brow + 8) * N + bn + bcol);
        }
#pragma unroll
        for (int kk = 0; kk < 16; ++kk) {
            float af[8], bf[8];
            *(float4*)&af[0] = *(const float4*)&As[buf][kk][ty*4];
            *(float4*)&af[4] = *(const float4*)&As[buf][kk][64+ty*4];
            *(float4*)&bf[0] = *(const float4*)&Bs[buf][kk][tx*4];
            *(float4*)&bf[4] = *(const float4*)&Bs[buf][kk][64+tx*4];
#pragma unroll
            for (int i = 0; i < 8; ++i)
#pragma unroll
                for (int j = 0; j < 8; ++j)
                    acc[i][j] = fmaf(af[i], bf[j], acc[i][j]);
        }
        if (t + 1 < ktiles) {
            buf ^= 1;
            As[buf][ak+0][arow]=ra0.x; As[buf][ak+1][arow]=ra0.y; As[buf][ak+2][arow]=ra0.z; As[buf][ak+3][arow]=ra0.w;
            As[buf][ak+0][64+arow]=ra1.x; As[buf][ak+1][64+arow]=ra1.y; As[buf][ak+2][64+arow]=ra1.z; As[buf][ak+3][64+arow]=ra1.w;
            *(float4*)&Bs[buf][brow][bcol] = rb0; *(float4*)&Bs[buf][brow+8][bcol] = rb1;
            __syncthreads();
        }
    }
#pragma unroll
    for (int i2 = 0; i2 < 2; ++i2)
#pragma unroll
        for (int i = 0; i < 4; ++i) {
            int row = bm + i2 * 64 + ty * 4 + i;
            if (row >= M) continue;
#pragma unroll
            for (int j2 = 0; j2 < 2; ++j2)
#pragma unroll
                for (int j = 0; j < 4; ++j) {
                    int col = bn + j2 * 64 + tx * 4 + j;
                    float v = acc[i2*4+i][j2*4+j];
                    if (bias) v += bias[col];
                    C[(size_t)row * N + col] = v;
                }
        }
}

// ------------------------- HMMA GEMM + fused LSTM cell ----------------------
// CTA 128M x 128N, 256 threads, 8 warps (2m x 4n), warp tile 64x32.
// fp16 2-limb, 3 products. wn-warps share A lines (L1 hits within the launch).
// MODE 1: layer0 (gates += latbase + embtab[tok]; cell -> c0; h0 frags at ktOff 0)
// MODE 2: layer1 (gates += bias; cell -> c1; h1 frags at ktOff 16; h1f fp32)
template <int MODE>
__global__ __launch_bounds__(256, 1)
void mma_lstm(const unsigned* __restrict__ A0H, const unsigned* __restrict__ A0M,
              const unsigned* __restrict__ A1H, const unsigned* __restrict__ A1M,
              int ksw, int NKT,
              const unsigned* __restrict__ BF, int BW,
              const float* __restrict__ pre, const float* __restrict__ emb,
              const float* __restrict__ bias, const int* __restrict__ tok,
              float* __restrict__ cst,
              unsigned* __restrict__ oAH, unsigned* __restrict__ oAM, int ktOff,
              float* __restrict__ h1f) {
    const int lane = threadIdx.x & 31, w = threadIdx.x >> 5;
    const int wm = w >> 2, wn = w & 3;
    const int mtBase = blockIdx.y * 8 + wm * 4;
    const int ntBase = blockIdx.x * 16 + wn * 4;

    float acc[4][4][4];
#pragma unroll
    for (int m = 0; m < 4; ++m)
#pragma unroll
        for (int n = 0; n < 4; ++n)
#pragma unroll
            for (int r = 0; r < 4; ++r) acc[m][n][r] = 0.f;

#pragma unroll 4
    for (int kt = 0; kt < NKT; ++kt) {
        const unsigned* AH = (kt < ksw) ? A0H : A1H;
        const unsigned* AM = (kt < ksw) ? A0M : A1M;
        uint4 a[2][4];
#pragma unroll
        for (int m = 0; m < 4; ++m) {
            unsigned sl = (((unsigned)(mtBase + m) * 32 + kt) * 32 + lane) * 4;
            a[0][m] = *(const uint4*)(AH + sl);
            a[1][m] = *(const uint4*)(AM + sl);
        }
        uint2 b[2][4];
#pragma unroll
        for (int n = 0; n < 4; ++n) {
            unsigned sl = (((unsigned)(ntBase + n) * NKT + kt) * 32 + lane) * 2;
            b[0][n] = *(const uint2*)(BF + sl);
            b[1][n] = *(const uint2*)(BF + BW + sl);
        }
        const int LA[3] = {0, 0, 1};
        const int LB[3] = {0, 1, 0};
#pragma unroll
        for (int pi = 0; pi < 3; ++pi)
#pragma unroll
            for (int m = 0; m < 4; ++m)
#pragma unroll
                for (int n = 0; n < 4; ++n)
                    mma16816(acc[m][n], a[LA[pi]][m], b[LB[pi]][n]);
    }

    // ---- fused LSTM epilogue ----
    const int group = blockIdx.x * 4 + wn;            // 0..31 gate-group (32 cols each)
    const int u0 = 2 * (lane & 3);                    // unit pair within group
    const int j0 = group * 8 + u0;                    // global unit (even)
    const int ktA = ktOff + (group >> 1);
    const int regB = (group & 1) * 2;
    float4 bv0, bv1;
    if (MODE == 2) {
        bv0 = *(const float4*)(bias + j0 * 4);
        bv1 = *(const float4*)(bias + j0 * 4 + 4);
    }
#pragma unroll
    for (int m = 0; m < 4; ++m)
#pragma unroll
        for (int rh = 0; rh < 2; ++rh) {
            int row = blockIdx.y * 128 + wm * 64 + m * 16 + (lane >> 2) + rh * 8;
            float g0[4], g1[4];
#pragma unroll
            for (int g = 0; g < 4; ++g) { g0[g] = acc[m][g][rh * 2]; g1[g] = acc[m][g][rh * 2 + 1]; }
            if (MODE == 1) {
                int tk = tok[row];
                const float* pr = pre + (size_t)row * G_ + j0 * 4;
                const float* er = emb + (size_t)tk * G_ + j0 * 4;
                float4 p0 = *(const float4*)pr, p1 = *(const float4*)(pr + 4);
                float4 e0 = *(const float4*)er, e1 = *(const float4*)(er + 4);
                g0[0] = g0[0] + p0.x + e0.x; g0[1] = g0[1] + p0.y + e0.y;
                g0[2] = g0[2] + p0.z + e0.z; g0[3] = g0[3] + p0.w + e0.w;
                g1[0] = g1[0] + p1.x + e1.x; g1[1] = g1[1] + p1.y + e1.y;
                g1[2] = g1[2] + p1.z + e1.z; g1[3] = g1[3] + p1.w + e1.w;
            } else {
                g0[0] += bv0.x; g0[1] += bv0.y; g0[2] += bv0.z; g0[3] += bv0.w;
                g1[0] += bv1.x; g1[1] += bv1.y; g1[2] += bv1.z; g1[3] += bv1.w;
            }
            float2 cv = *(const float2*)(cst + (size_t)row * H_ + j0);
            float cn0 = sigmoid_xla(g0[1]) * cv.x + sigmoid_xla(g0[0]) * tanh_xla(g0[2]);
            float hn0 = sigmoid_xla(g0[3]) * tanh_xla(cn0);
            float cn1 = sigmoid_xla(g1[1]) * cv.y + sigmoid_xla(g1[0]) * tanh_xla(g1[2]);
            float hn1 = sigmoid_xla(g1[3]) * tanh_xla(cn1);
            *(float2*)(cst + (size_t)row * H_ + j0) = make_float2(cn0, cn1);
            __half h0h, h0m, h1h, h1m;
            split2(hn0, h0h, h0m);
            split2(hn1, h1h, h1m);
            unsigned slot = (((unsigned)(row >> 4) * 32 + ktA) * 32 + lane) * 4 + regB + rh;
            oAH[slot] = (unsigned)__half_as_ushort(h0h) | ((unsigned)__half_as_ushort(h1h) << 16);
            oAM[slot] = (unsigned)__half_as_ushort(h0m) | ((unsigned)__half_as_ushort(h1m) << 16);
            if (MODE == 2)
                *(float2*)(h1f + (size_t)row * H_ + j0) = make_float2(hn0, hn1);
        }
}

// ------------------------- logits + categorical sample ---------------------
__global__ __launch_bounds__(256)
void logits_sample(const float* __restrict__ h, const float* __restrict__ Woutt,
                   const float* __restrict__ bout, float* __restrict__ out,
                   int* __restrict__ tok, int t) {
    __shared__ float sW[64][100];
    __shared__ float sH[16][64];
    const int tid = threadIdx.x, lane = tid & 31, w = tid >> 5;
    const int baseRow = blockIdx.x * 16;
    const uint2 key = g_keys[t];
    float acc[2][4] = {};

    for (int kc = 0; kc < 4; ++kc) {
        for (int i = tid; i < 6400; i += 256) {
            int kr = i / 100, v = i - kr * 100;
            sW[kr][v] = Woutt[(kc * 64 + kr) * 100 + v];
        }
        for (int i = tid; i < 1024; i += 256) {
            int r = i >> 6, k = i & 63;
            sH[r][k] = h[(size_t)(baseRow + r) * H_ + kc * 64 + k];
        }
        __syncthreads();
#pragma unroll
        for (int rr = 0; rr < 2; ++rr) {
            int r = w * 2 + rr;
#pragma unroll 8
            for (int k = 0; k < 64; ++k) {
                float hk = sH[r][k];
                acc[rr][0] = fmaf(hk, sW[k][lane],      acc[rr][0]);
                acc[rr][1] = fmaf(hk, sW[k][lane + 32], acc[rr][1]);
                acc[rr][2] = fmaf(hk, sW[k][lane + 64], acc[rr][2]);
                if (lane < 4) acc[rr][3] = fmaf(hk, sW[k][lane + 96], acc[rr][3]);
            }
        }
        __syncthreads();
    }

    for (int rr = 0; rr < 2; ++rr) {
        int row = baseRow + w * 2 + rr;
        float bestV = -__int_as_float(0x7f800000);
        int bestI = 0x7fffffff;
        float* orow = out + (size_t)row * (T_ * V_) + t * V_;
#pragma unroll
        for (int j = 0; j < 4; ++j) {
            int v = lane + 32 * j;
            if (v < V_) {
                float lg = acc[rr][j] + bout[v];
                orow[v] = lg;
                uint32_t o0, o1;
                tf2x32(key.x, key.y, 0u, (uint32_t)(row * V_ + v), o0, o1);
                uint32_t bits = o0 ^ o1;
                float f = __uint_as_float((bits >> 9) | 0x3f800000u) - 1.0f;
                float u = fmaxf(f, 1.17549435e-38f);
                float gum = -__nv_logf(-__nv_logf(u));
                float val = gum + lg;
                if (val > bestV || (val == bestV && v < bestI)) { bestV = val; bestI = v; }
            }
        }
        for (int off = 16; off; off >>= 1) {
            float ov = __shfl_down_sync(0xffffffffu, bestV, off);
            int   oi = __shfl_down_sync(0xffffffffu, bestI, off);
            if (ov > bestV || (ov == bestV && oi < bestI)) { bestV = ov; bestI = oi; }
        }
        if (lane == 0) tok[row] = bestI;
    }
}

// ------------------------- host launch --------------------------------------
static void* symA(const void* s) { void* p = nullptr; cudaGetSymbolAddress(&p, s); return p; }

extern "C" void kernel_launch(void* const* d_in, const int* in_sizes, int n_in,
                              void* d_out, int out_size) {
    (void)in_sizes; (void)n_in; (void)out_size;
    const float* latent    = (const float*)d_in[0];
    const float* embedding = (const float*)d_in[1];
    const float* W_lp      = (const float*)d_in[2];
    const float* b_lp      = (const float*)d_in[3];
    const float* W_ih0     = (const float*)d_in[4];
    const float* W_hh0     = (const float*)d_in[5];
    const float* b_ih0     = (const float*)d_in[6];
    const float* b_hh0     = (const float*)d_in[7];
    const float* W_ih1     = (const float*)d_in[8];
    const float* W_hh1     = (const float*)d_in[9];
    const float* b_ih1     = (const float*)d_in[10];
    const float* b_hh1     = (const float*)d_in[11];
    const float* W_out     = (const float*)d_in[12];
    const float* b_out     = (const float*)d_in[13];
    float* out = (float*)d_out;

    float* latbase = (float*)symA(g_latbase);
    float* embtab  = (float*)symA(g_embtab);
    float* lath    = (float*)symA(g_lath);
    float* h1f     = (float*)symA(g_h1f);
    float* c0      = (float*)symA(g_c0);
    float* c1      = (float*)symA(g_c1);
    float* wlatt   = (float*)symA(g_Wih0latt);
    float* wlpt    = (float*)symA(g_Wlpt);
    float* woutt   = (float*)symA(g_Woutt);
    float* bias01  = (float*)symA(g_bias01);
    float* bias1p  = (float*)symA(g_bias1p);
    int*   tok     = (int*)symA(g_tok);
    unsigned* AH = (unsigned*)symA(g_AH);
    unsigned* AM = (unsigned*)symA(g_AM);
    unsigned* B0 = (unsigned*)symA(g_B0);
    unsigned* B1 = (unsigned*)symA(g_B1);

    // One fused setup kernel (covers B_*H_ = 2M elements, the largest range)
    setup_kernel<<<(B_ * H_) / 256, 256>>>(W_ih0, W_lp, W_out, b_ih0, b_hh0, b_ih1, b_hh1,
                                           W_hh0, W_ih1, W_hh1, embedding);

    // lat_h = latent @ W_lp^T + b_lp ; latbase = lat_h @ W_ih0[:,256:]^T + bias01 (p2)
    sgemm0<<<dim3(E_ / 128, B_ / 128), 256>>>(latent, LD_, wlpt, b_lp, lath, B_, E_, LD_);
    sgemm0<<<dim3(G_ / 128, B_ / 128), 256>>>(lath, E_, wlatt, bias01, latbase, B_, G_, E_);

    int p = 0;
    for (int t = 0; t < T_; ++t) {
        const int q = p ^ 1;
        unsigned *pH = AH + (size_t)p * AFW, *pM = AM + (size_t)p * AFW;
        unsigned *qH = AH + (size_t)q * AFW, *qM = AM + (size_t)q * AFW;
        // layer 0: gates = h0_prev @ Whh0^T + latbase + embtab[tok] -> c0, h0 frags (kt 0-15 of q)
        mma_lstm<1><<<dim3(8, 64), 256>>>(
            pH, pM, pH, pM, 16, 16, B0, B0W,
            latbase, embtab, nullptr, tok, c0, qH, qM, 0, nullptr);
        // layer 1: gates = [h0_new | h1_prev] @ W1^T + bias1 -> c1, h1 frags (kt 16-31 of q), h1f
        mma_lstm<2><<<dim3(8, 64), 256>>>(
            qH, qM, pH, pM, 16, 32, B1, B1W,
            nullptr, nullptr, bias1p, tok, c1, qH, qM, 16, h1f);
        logits_sample<<<B_ / 16, 256>>>(h1f, woutt, b_out, out, tok, t);
        p ^= 1;
    }
}

// round 16
// speedup vs baseline: 1.3499x; 1.3499x over previous
#include <cuda_runtime.h>
#include <cuda_fp16.h>
#include <cstdint>
#include <cstddef>

extern "C" __device__ float __nv_logf(float);

#define B_  8192
#define LD_ 512
#define V_  100
#define E_  256
#define H_  256
#define G_  1024   // 4*H
#define T_  100

// A-fragment buffer: [mtile(512)][ktile(32)][lane(32)][reg(4)] uint32 (fp16x2)
#define AFW (512 * 32 * 32 * 4)
// B-fragment buffers: [ntile(128)][ktile(KT)][lane(32)][reg(2)] uint32
#define B0W (128 * 16 * 32 * 2)
#define B1W (128 * 32 * 32 * 2)

// ------------------------- device scratch ----------------------------------
__device__ unsigned g_AH[2 * AFW];     // hi limb, ping-pong
__device__ unsigned g_AM[2 * AFW];     // mid limb, ping-pong
__device__ unsigned g_B0[2 * B0W];     // 2 limbs concatenated
__device__ unsigned g_B1[2 * B1W];
__device__ float g_latbase[B_ * G_];   // [row][j*4+g]  (unit-major p2 layout)
__device__ float g_embtab [V_ * G_];   // [v][j*4+g]
__device__ float g_lath   [B_ * E_];
__device__ float g_h1f    [B_ * H_];   // fp32 h1 for logits
__device__ float g_c0     [B_ * H_];
__device__ float g_c1     [B_ * H_];
__device__ float g_Wih0latt[E_ * G_];
__device__ float g_Wlpt   [LD_ * E_];
__device__ float g_Woutt  [H_ * V_];
__device__ float g_bias01 [G_];        // p2 layout
__device__ float g_bias1p [G_];        // p2 layout
__device__ int   g_tok    [B_];
__device__ uint2 g_keys   [T_];

// ------------------------- XLA-matching elementwise math -------------------
__device__ __forceinline__ float tanh_xla(float x) {
    float ax = fabsf(x);
    float xc = fminf(fmaxf(x, -7.99881172180175781f), 7.99881172180175781f);
    float x2 = xc * xc;
    float nm = -2.76076847742355e-16f;
    nm = fmaf(x2, nm,  2.00018790482477e-13f);
    nm = fmaf(x2, nm, -8.60467152213735e-11f);
    nm = fmaf(x2, nm,  5.12229709037114e-08f);
    nm = fmaf(x2, nm,  1.48572235717979e-05f);
    nm = fmaf(x2, nm,  6.37261928875436e-04f);
    nm = fmaf(x2, nm,  4.89352455891786e-03f);
    nm = xc * nm;
    float dn = 1.19825839466702e-06f;
    dn = fmaf(x2, dn,  1.18534705686654e-04f);
    dn = fmaf(x2, dn,  2.26843463243900e-03f);
    dn = fmaf(x2, dn,  4.89352518554385e-03f);
    return (ax < 0.0004f) ? x : (nm / dn);
}
__device__ __forceinline__ float sigmoid_xla(float x) {
    return 0.5f * tanh_xla(0.5f * x) + 0.5f;
}
// 2-limb fp16 split: a = h + m + l, |l| <= 2^-22 |a| (approx)
__device__ __forceinline__ void split2(float a, __half& h, __half& m) {
    h = __float2half_rn(a);
    m = __float2half_rn(a - __half2float(h));
}

// ------------------------- threefry2x32 ------------------------------------
__device__ __forceinline__ void tf2x32(uint32_t k0, uint32_t k1,
                                       uint32_t x0, uint32_t x1,
                                       uint32_t& o0, uint32_t& o1) {
    uint32_t k2 = k0 ^ k1 ^ 0x1BD11BDAu;
    x0 += k0; x1 += k1;
#define TFR4(a,b,c,d) \
    x0 += x1; x1 = (x1 << a) | (x1 >> (32 - a)); x1 ^= x0; \
    x0 += x1; x1 = (x1 << b) | (x1 >> (32 - b)); x1 ^= x0; \
    x0 += x1; x1 = (x1 << c) | (x1 >> (32 - c)); x1 ^= x0; \
    x0 += x1; x1 = (x1 << d) | (x1 >> (32 - d)); x1 ^= x0;
    TFR4(13,15,26,6)  x0 += k1; x1 += k2 + 1u;
    TFR4(17,29,16,24) x0 += k2; x1 += k0 + 2u;
    TFR4(13,15,26,6)  x0 += k0; x1 += k1 + 3u;
    TFR4(17,29,16,24) x0 += k1; x1 += k2 + 4u;
    TFR4(13,15,26,6)  x0 += k2; x1 += k0 + 5u;
#undef TFR4
    o0 = x0; o1 = x1;
}

// ------------------------- HMMA m16n8k16 fp16 ------------------------------
__device__ __forceinline__ void mma16816(float* d, const uint4& a, const uint2& b) {
    asm volatile("mma.sync.aligned.m16n8k16.row.col.f32.f16.f16.f32 "
        "{%0,%1,%2,%3}, {%4,%5,%6,%7}, {%8,%9}, {%0,%1,%2,%3};"
        : "+f"(d[0]), "+f"(d[1]), "+f"(d[2]), "+f"(d[3])
        : "r"(a.x), "r"(a.y), "r"(a.z), "r"(a.w), "r"(b.x), "r"(b.y));
}

// ------------------------- cp.async helpers --------------------------------
__device__ __forceinline__ uint32_t smem_u32(const void* p) {
    return (uint32_t)__cvta_generic_to_shared(p);
}
#define CP_ASYNC16(dst, src) \
    asm volatile("cp.async.cg.shared.global [%0], [%1], 16;" :: "r"(dst), "l"(src))
#define CP_COMMIT() asm volatile("cp.async.commit_group;" ::: "memory")
#define CP_WAIT1()  asm volatile("cp.async.wait_group 1;" ::: "memory")

// ------------------------- fused setup kernel ------------------------------
// p2 permutation: original gate col n = g*256 + j  ->  p2 = j*4 + g
// B-frag slot: nt=p>>3, lane=(p&7)*4+((k&7)>>1), reg=(k>>3)&1, half=k&1, kt=k>>4.
__global__ void setup_kernel(const float* __restrict__ Wih0, const float* __restrict__ Wlp,
                             const float* __restrict__ Wout,
                             const float* __restrict__ bih0, const float* __restrict__ bhh0,
                             const float* __restrict__ bih1, const float* __restrict__ bhh1,
                             const float* __restrict__ Whh0, const float* __restrict__ Wih1,
                             const float* __restrict__ Whh1, const float* __restrict__ emb) {
    int i = blockIdx.x * blockDim.x + threadIdx.x;
    if (i < G_ * H_) {                 // i = n*256 + k
        int n = i >> 8, k = i & 255;
        int p = (n & 255) * 4 + (n >> 8);
        g_Wih0latt[k * G_ + p] = Wih0[n * 512 + 256 + k];
    }
    if (i < E_ * LD_) {
        int n = i >> 9, k = i & 511;
        g_Wlpt[k * E_ + n] = Wlp[i];
    }
    if (i < V_ * H_) {
        int v = i >> 8, k = i & 255;
        g_Woutt[k * V_ + v] = Wout[i];
    }
    if (i < G_) {
        int p = (i & 255) * 4 + (i >> 8);
        g_bias01[p] = bih0[i] + bhh0[i];
        g_bias1p[p] = bih1[i] + bhh1[i];
    }
    if (i < G_ * 512) {                  // B1 frags: layer 1, K = 512
        int n = i >> 9, k = i & 511;
        float wv = (k < 256) ? Wih1[n * 256 + k] : Whh1[n * 256 + k - 256];
        int g = n >> 8, j = n & 255;
        int p = (j >> 3) * 32 + g * 8 + (j & 7);
        int nt = p >> 3;
        int lanei = (p & 7) * 4 + ((k & 7) >> 1);
        int reg = (k >> 3) & 1, half = k & 1, kt = k >> 4;
        size_t idx = ((((size_t)nt * 32 + kt) * 32 + lanei) * 2 + reg) * 2 + half;
        __half hh, mm; split2(wv, hh, mm);
        __half* b = reinterpret_cast<__half*>(g_B1);
        b[idx] = hh; b[(size_t)2 * B1W + idx] = mm;
    }
    if (i < G_ * 256) {                  // B0 frags: layer 0, K = 256
        int n = i >> 8, k = i & 255;
        float wv = Whh0[i];
        int g = n >> 8, j = n & 255;
        int p = (j >> 3) * 32 + g * 8 + (j & 7);
        int nt = p >> 3;
        int lanei = (p & 7) * 4 + ((k & 7) >> 1);
        int reg = (k >> 3) & 1, half = k & 1, kt = k >> 4;
        size_t idx = ((((size_t)nt * 16 + kt) * 32 + lanei) * 2 + reg) * 2 + half;
        __half hh, mm; split2(wv, hh, mm);
        __half* b = reinterpret_cast<__half*>(g_B0);
        b[idx] = hh; b[(size_t)2 * B0W + idx] = mm;
    }
    if (i < V_ * 1024) {                 // embtab: 100x1024 dot products, K=256
        int v = i >> 10, p = i & 1023;
        int n = (p & 3) * 256 + (p >> 2);
        const float* er = emb + v * E_;
        const float* wr = Wih0 + n * 512;
        float s = 0.f;
        for (int k = 0; k < 256; ++k) s = fmaf(er[k], wr[k], s);
        g_embtab[v * G_ + p] = s;
    }
    if (i < AFW / 4) {    // zero ping buffer (buffer 0) of A-frag limbs
        ((uint4*)g_AH)[i] = make_uint4(0, 0, 0, 0);
        ((uint4*)g_AM)[i] = make_uint4(0, 0, 0, 0);
    }
    if (i < B_ * H_) { g_c0[i] = 0.0f; g_c1[i] = 0.0f; }
    if (i < B_) g_tok[i] = 1;                       // START_TOKEN
    if (i < T_) {
        uint32_t o0, o1;
        tf2x32(0u, 42u, 0u, (uint32_t)i, o0, o1);   // partitionable split
        g_keys[i] = make_uint2(o0, o1);
    }
}

// ------------------------- fp32 precompute GEMM (outside loop) --------------
__global__ __launch_bounds__(256, 2)
void sgemm0(const float* __restrict__ A, int lda, const float* __restrict__ Wt,
            const float* __restrict__ bias, float* __restrict__ C, int M, int N, int K) {
    const int bm = blockIdx.y * 128, bn = blockIdx.x * 128;
    const int tid = threadIdx.x, tx = tid & 15, ty = tid >> 4;
    __shared__ float As[2][16][128];
    __shared__ float Bs[2][16][128];
    float acc[8][8] = {};
    const int arow = tid >> 2, ak = (tid & 3) * 4;
    const int brow = tid >> 5, bcol = (tid & 31) * 4;
    const int r0 = min(bm + arow, M - 1);
    const int r1 = min(bm + 64 + arow, M - 1);
    float4 ra0 = *(const float4*)(A + (size_t)r0 * lda + ak);
    float4 ra1 = *(const float4*)(A + (size_t)r1 * lda + ak);
    float4 rb0 = *(const float4*)(Wt + (size_t)brow * N + bn + bcol);
    float4 rb1 = *(const float4*)(Wt + (size_t)(brow + 8) * N + bn + bcol);
    int buf = 0;
    As[0][ak+0][arow]=ra0.x; As[0][ak+1][arow]=ra0.y; As[0][ak+2][arow]=ra0.z; As[0][ak+3][arow]=ra0.w;
    As[0][ak+0][64+arow]=ra1.x; As[0][ak+1][64+arow]=ra1.y; As[0][ak+2][64+arow]=ra1.z; As[0][ak+3][64+arow]=ra1.w;
    *(float4*)&Bs[0][brow][bcol] = rb0; *(float4*)&Bs[0][brow+8][bcol] = rb1;
    __syncthreads();
    const int ktiles = K >> 4;
    for (int t = 0; t < ktiles; ++t) {
        if (t + 1 < ktiles) {
            int ko = (t + 1) * 16;
            ra0 = *(const float4*)(A + (size_t)r0 * lda + ko + ak);
            ra1 = *(const float4*)(A + (size_t)r1 * lda + ko + ak);
            rb0 = *(const float4*)(Wt + (size_t)(ko + brow) * N + bn + bcol);
            rb1 = *(const float4*)(Wt + (size_t)(ko + brow + 8) * N + bn + bcol);
        }
#pragma unroll
        for (int kk = 0; kk < 16; ++kk) {
            float af[8], bf[8];
            *(float4*)&af[0] = *(const float4*)&As[buf][kk][ty*4];
            *(float4*)&af[4] = *(const float4*)&As[buf][kk][64+ty*4];
            *(float4*)&bf[0] = *(const float4*)&Bs[buf][kk][tx*4];
            *(float4*)&bf[4] = *(const float4*)&Bs[buf][kk][64+tx*4];
#pragma unroll
            for (int i = 0; i < 8; ++i)
#pragma unroll
                for (int j = 0; j < 8; ++j)
                    acc[i][j] = fmaf(af[i], bf[j], acc[i][j]);
        }
        if (t + 1 < ktiles) {
            buf ^= 1;
            As[buf][ak+0][arow]=ra0.x; As[buf][ak+1][arow]=ra0.y; As[buf][ak+2][arow]=ra0.z; As[buf][ak+3][arow]=ra0.w;
            As[buf][ak+0][64+arow]=ra1.x; As[buf][ak+1][64+arow]=ra1.y; As[buf][ak+2][64+arow]=ra1.z; As[buf][ak+3][64+arow]=ra1.w;
            *(float4*)&Bs[buf][brow][bcol] = rb0; *(float4*)&Bs[buf][brow+8][bcol] = rb1;
            __syncthreads();
        }
    }
#pragma unroll
    for (int i2 = 0; i2 < 2; ++i2)
#pragma unroll
        for (int i = 0; i < 4; ++i) {
            int row = bm + i2 * 64 + ty * 4 + i;
            if (row >= M) continue;
#pragma unroll
            for (int j2 = 0; j2 < 2; ++j2)
#pragma unroll
                for (int j = 0; j < 4; ++j) {
                    int col = bn + j2 * 64 + tx * 4 + j;
                    float v = acc[i2*4+i][j2*4+j];
                    if (bias) v += bias[col];
                    C[(size_t)row * N + col] = v;
                }
        }
}

// ------------------------- HMMA GEMM + fused LSTM cell ----------------------
// CTA 128M x 64N, 128 threads, 4 warps (2m x 2n), warp tile 64x32.
// cp.async 3-stage smem pipeline: gmem->smem (LDGSTS) -> regs (LDS) -> mma.
// fp16 2-limb, 3 products. __launch_bounds__(128,3) => 12 warps/SM.
// MODE 1: layer0 (gates += latbase + embtab[tok]; cell -> c0; h0 frags at ktOff 0)
// MODE 2: layer1 (gates += bias; cell -> c1; h1 frags at ktOff 16; h1f fp32)
template <int MODE>
__global__ __launch_bounds__(128, 3)
void mma_lstm(const unsigned* __restrict__ A0H, const unsigned* __restrict__ A0M,
              const unsigned* __restrict__ A1H, const unsigned* __restrict__ A1M,
              int ksw, int NKT,
              const unsigned* __restrict__ BF, int BW,
              const float* __restrict__ pre, const float* __restrict__ emb,
              const float* __restrict__ bias, const int* __restrict__ tok,
              float* __restrict__ cst,
              unsigned* __restrict__ oAH, unsigned* __restrict__ oAM, int ktOff,
              float* __restrict__ h1f) {
    __shared__ unsigned sA[3][2][8][128];   // [stage][limb][mt][lane*4+reg]
    __shared__ unsigned sB[3][2][8][64];    // [stage][limb][nt][lane*2+reg]
    const int tid = threadIdx.x;
    const int lane = tid & 31, w = tid >> 5;
    const int wm = w >> 1, wn = w & 1;
    const int mtCTA = blockIdx.y * 8;
    const int ntCTA = blockIdx.x * 8;
    const uint32_t sAb = smem_u32(&sA[0][0][0][0]);
    const uint32_t sBb = smem_u32(&sB[0][0][0][0]);

    // A copy: 256 16B-chunks per limb; chunk c: mt=c>>5, off=(c&31)*4
    // B copy: 128 16B-chunks per limb; chunk c: nt=c>>4, off=(c&15)*4
    auto copy_stage = [&](int s, int kt) {
        const unsigned* AH = (kt < ksw) ? A0H : A1H;
        const unsigned* AM = (kt < ksw) ? A0M : A1M;
#pragma unroll
        for (int j = 0; j < 2; ++j) {
            int c = tid + j * 128;
            int mt = c >> 5, off = (c & 31) * 4;
            size_t g = ((size_t)(mtCTA + mt) * 32 + kt) * 128 + off;
            uint32_t dH = sAb + (((s * 2 + 0) * 8 + mt) * 128 + off) * 4;
            uint32_t dM = sAb + (((s * 2 + 1) * 8 + mt) * 128 + off) * 4;
            CP_ASYNC16(dH, AH + g);
            CP_ASYNC16(dM, AM + g);
        }
        {
            int nt = tid >> 4, off = (tid & 15) * 4;
            size_t g = ((size_t)(ntCTA + nt) * NKT + kt) * 64 + off;
            uint32_t d0 = sBb + (((s * 2 + 0) * 8 + nt) * 64 + off) * 4;
            uint32_t d1 = sBb + (((s * 2 + 1) * 8 + nt) * 64 + off) * 4;
            CP_ASYNC16(d0, BF + g);
            CP_ASYNC16(d1, BF + BW + g);
        }
    };

    float acc[4][4][4];
#pragma unroll
    for (int m = 0; m < 4; ++m)
#pragma unroll
        for (int n = 0; n < 4; ++n)
#pragma unroll
            for (int r = 0; r < 4; ++r) acc[m][n][r] = 0.f;

    // prologue: stages 0,1 in flight
    copy_stage(0, 0); CP_COMMIT();
    copy_stage(1, 1); CP_COMMIT();

    int sUse = 0;
#pragma unroll 1
    for (int kt = 0; kt < NKT; ++kt) {
        CP_WAIT1();            // stage kt complete (newest may be pending)
        __syncthreads();       // all warps see stage; prior LDS of old slot drained

        uint4 a[2][4];
        uint2 b[2][4];
#pragma unroll
        for (int m = 0; m < 4; ++m) {
            a[0][m] = *(const uint4*)&sA[sUse][0][wm * 4 + m][lane * 4];
            a[1][m] = *(const uint4*)&sA[sUse][1][wm * 4 + m][lane * 4];
        }
#pragma unroll
        for (int n = 0; n < 4; ++n) {
            b[0][n] = *(const uint2*)&sB[sUse][0][wn * 4 + n][lane * 2];
            b[1][n] = *(const uint2*)&sB[sUse][1][wn * 4 + n][lane * 2];
        }

        // issue next copy into slot (sUse+2)%3 (stage kt-1's slot, consumed last iter)
        if (kt + 2 < NKT) {
            int sc = sUse + 2; if (sc >= 3) sc -= 3;
            copy_stage(sc, kt + 2);
        }
        CP_COMMIT();           // one group per iteration (possibly empty)

        const int LA[3] = {0, 0, 1};
        const int LB[3] = {0, 1, 0};
#pragma unroll
        for (int pi = 0; pi < 3; ++pi)
#pragma unroll
            for (int m = 0; m < 4; ++m)
#pragma unroll
                for (int n = 0; n < 4; ++n)
                    mma16816(acc[m][n], a[LA[pi]][m], b[LB[pi]][n]);

        sUse = (sUse == 2) ? 0 : sUse + 1;
    }

    // ---- fused LSTM epilogue ----
    const int group = blockIdx.x * 2 + wn;            // 0..31 gate-group (32 cols each)
    const int u0 = 2 * (lane & 3);                    // unit pair within group
    const int j0 = group * 8 + u0;                    // global unit (even)
    const int ktA = ktOff + (group >> 1);
    const int regB = (group & 1) * 2;
    float4 bv0, bv1;
    if (MODE == 2) {
        bv0 = *(const float4*)(bias + j0 * 4);
        bv1 = *(const float4*)(bias + j0 * 4 + 4);
    }
#pragma unroll
    for (int m = 0; m < 4; ++m)
#pragma unroll
        for (int rh = 0; rh < 2; ++rh) {
            int row = blockIdx.y * 128 + wm * 64 + m * 16 + (lane >> 2) + rh * 8;
            float g0[4], g1[4];
#pragma unroll
            for (int g = 0; g < 4; ++g) { g0[g] = acc[m][g][rh * 2]; g1[g] = acc[m][g][rh * 2 + 1]; }
            if (MODE == 1) {
                int tk = tok[row];
                const float* pr = pre + (size_t)row * G_ + j0 * 4;
                const float* er = emb + (size_t)tk * G_ + j0 * 4;
                float4 p0 = *(const float4*)pr, p1 = *(const float4*)(pr + 4);
                float4 e0 = *(const float4*)er, e1 = *(const float4*)(er + 4);
                g0[0] = g0[0] + p0.x + e0.x; g0[1] = g0[1] + p0.y + e0.y;
                g0[2] = g0[2] + p0.z + e0.z; g0[3] = g0[3] + p0.w + e0.w;
                g1[0] = g1[0] + p1.x + e1.x; g1[1] = g1[1] + p1.y + e1.y;
                g1[2] = g1[2] + p1.z + e1.z; g1[3] = g1[3] + p1.w + e1.w;
            } else {
                g0[0] += bv0.x; g0[1] += bv0.y; g0[2] += bv0.z; g0[3] += bv0.w;
                g1[0] += bv1.x; g1[1] += bv1.y; g1[2] += bv1.z; g1[3] += bv1.w;
            }
            float2 cv = *(const float2*)(cst + (size_t)row * H_ + j0);
            float cn0 = sigmoid_xla(g0[1]) * cv.x + sigmoid_xla(g0[0]) * tanh_xla(g0[2]);
            float hn0 = sigmoid_xla(g0[3]) * tanh_xla(cn0);
            float cn1 = sigmoid_xla(g1[1]) * cv.y + sigmoid_xla(g1[0]) * tanh_xla(g1[2]);
            float hn1 = sigmoid_xla(g1[3]) * tanh_xla(cn1);
            *(float2*)(cst + (size_t)row * H_ + j0) = make_float2(cn0, cn1);
            __half h0h, h0m, h1h, h1m;
            split2(hn0, h0h, h0m);
            split2(hn1, h1h, h1m);
            unsigned slot = (((unsigned)(row >> 4) * 32 + ktA) * 32 + lane) * 4 + regB + rh;
            oAH[slot] = (unsigned)__half_as_ushort(h0h) | ((unsigned)__half_as_ushort(h1h) << 16);
            oAM[slot] = (unsigned)__half_as_ushort(h0m) | ((unsigned)__half_as_ushort(h1m) << 16);
            if (MODE == 2)
                *(float2*)(h1f + (size_t)row * H_ + j0) = make_float2(hn0, hn1);
        }
}

// ------------------------- logits + categorical sample ---------------------
__global__ __launch_bounds__(256)
void logits_sample(const float* __restrict__ h, const float* __restrict__ Woutt,
                   const float* __restrict__ bout, float* __restrict__ out,
                   int* __restrict__ tok, int t) {
    __shared__ float sW[64][100];
    __shared__ float sH[16][64];
    const int tid = threadIdx.x, lane = tid & 31, w = tid >> 5;
    const int baseRow = blockIdx.x * 16;
    const uint2 key = g_keys[t];
    float acc[2][4] = {};

    for (int kc = 0; kc < 4; ++kc) {
        for (int i = tid; i < 6400; i += 256) {
            int kr = i / 100, v = i - kr * 100;
            sW[kr][v] = Woutt[(kc * 64 + kr) * 100 + v];
        }
        for (int i = tid; i < 1024; i += 256) {
            int r = i >> 6, k = i & 63;
            sH[r][k] = h[(size_t)(baseRow + r) * H_ + kc * 64 + k];
        }
        __syncthreads();
#pragma unroll
        for (int rr = 0; rr < 2; ++rr) {
            int r = w * 2 + rr;
#pragma unroll 8
            for (int k = 0; k < 64; ++k) {
                float hk = sH[r][k];
                acc[rr][0] = fmaf(hk, sW[k][lane],      acc[rr][0]);
                acc[rr][1] = fmaf(hk, sW[k][lane + 32], acc[rr][1]);
                acc[rr][2] = fmaf(hk, sW[k][lane + 64], acc[rr][2]);
                if (lane < 4) acc[rr][3] = fmaf(hk, sW[k][lane + 96], acc[rr][3]);
            }
        }
        __syncthreads();
    }

    for (int rr = 0; rr < 2; ++rr) {
        int row = baseRow + w * 2 + rr;
        float bestV = -__int_as_float(0x7f800000);
        int bestI = 0x7fffffff;
        float* orow = out + (size_t)row * (T_ * V_) + t * V_;
#pragma unroll
        for (int j = 0; j < 4; ++j) {
            int v = lane + 32 * j;
            if (v < V_) {
                float lg = acc[rr][j] + bout[v];
                orow[v] = lg;
                uint32_t o0, o1;
                tf2x32(key.x, key.y, 0u, (uint32_t)(row * V_ + v), o0, o1);
                uint32_t bits = o0 ^ o1;
                float f = __uint_as_float((bits >> 9) | 0x3f800000u) - 1.0f;
                float u = fmaxf(f, 1.17549435e-38f);
                float gum = -__nv_logf(-__nv_logf(u));
                float val = gum + lg;
                if (val > bestV || (val == bestV && v < bestI)) { bestV = val; bestI = v; }
            }
        }
        for (int off = 16; off; off >>= 1) {
            float ov = __shfl_down_sync(0xffffffffu, bestV, off);
            int   oi = __shfl_down_sync(0xffffffffu, bestI, off);
            if (ov > bestV || (ov == bestV && oi < bestI)) { bestV = ov; bestI = oi; }
        }
        if (lane == 0) tok[row] = bestI;
    }
}

// ------------------------- host launch --------------------------------------
static void* symA(const void* s) { void* p = nullptr; cudaGetSymbolAddress(&p, s); return p; }

extern "C" void kernel_launch(void* const* d_in, const int* in_sizes, int n_in,
                              void* d_out, int out_size) {
    (void)in_sizes; (void)n_in; (void)out_size;
    const float* latent    = (const float*)d_in[0];
    const float* embedding = (const float*)d_in[1];
    const float* W_lp      = (const float*)d_in[2];
    const float* b_lp      = (const float*)d_in[3];
    const float* W_ih0     = (const float*)d_in[4];
    const float* W_hh0     = (const float*)d_in[5];
    const float* b_ih0     = (const float*)d_in[6];
    const float* b_hh0     = (const float*)d_in[7];
    const float* W_ih1     = (const float*)d_in[8];
    const float* W_hh1     = (const float*)d_in[9];
    const float* b_ih1     = (const float*)d_in[10];
    const float* b_hh1     = (const float*)d_in[11];
    const float* W_out     = (const float*)d_in[12];
    const float* b_out     = (const float*)d_in[13];
    float* out = (float*)d_out;

    float* latbase = (float*)symA(g_latbase);
    float* embtab  = (float*)symA(g_embtab);
    float* lath    = (float*)symA(g_lath);
    float* h1f     = (float*)symA(g_h1f);
    float* c0      = (float*)symA(g_c0);
    float* c1      = (float*)symA(g_c1);
    float* wlatt   = (float*)symA(g_Wih0latt);
    float* wlpt    = (float*)symA(g_Wlpt);
    float* woutt   = (float*)symA(g_Woutt);
    float* bias01  = (float*)symA(g_bias01);
    float* bias1p  = (float*)symA(g_bias1p);
    int*   tok     = (int*)symA(g_tok);
    unsigned* AH = (unsigned*)symA(g_AH);
    unsigned* AM = (unsigned*)symA(g_AM);
    unsigned* B0 = (unsigned*)symA(g_B0);
    unsigned* B1 = (unsigned*)symA(g_B1);

    // One fused setup kernel (covers B_*H_ = 2M elements, the largest range)
    setup_kernel<<<(B_ * H_) / 256, 256>>>(W_ih0, W_lp, W_out, b_ih0, b_hh0, b_ih1, b_hh1,
                                           W_hh0, W_ih1, W_hh1, embedding);

    // lat_h = latent @ W_lp^T + b_lp ; latbase = lat_h @ W_ih0[:,256:]^T + bias01 (p2)
    sgemm0<<<dim3(E_ / 128, B_ / 128), 256>>>(latent, LD_, wlpt, b_lp, lath, B_, E_, LD_);
    sgemm0<<<dim3(G_ / 128, B_ / 128), 256>>>(lath, E_, wlatt, bias01, latbase, B_, G_, E_);

    int p = 0;
    for (int t = 0; t < T_; ++t) {
        const int q = p ^ 1;
        unsigned *pH = AH + (size_t)p * AFW, *pM = AM + (size_t)p * AFW;
        unsigned *qH = AH + (size_t)q * AFW, *qM = AM + (size_t)q * AFW;
        // layer 0: gates = h0_prev @ Whh0^T + latbase + embtab[tok] -> c0, h0 frags (kt 0-15 of q)
        mma_lstm<1><<<dim3(16, 64), 128>>>(
            pH, pM, pH, pM, 16, 16, B0, B0W,
            latbase, embtab, nullptr, tok, c0, qH, qM, 0, nullptr);
        // layer 1: gates = [h0_new | h1_prev] @ W1^T + bias1 -> c1, h1 frags (kt 16-31 of q), h1f
        mma_lstm<2><<<dim3(16, 64), 128>>>(
            qH, qM, pH, pM, 16, 32, B1, B1W,
            nullptr, nullptr, bias1p, tok, c1, qH, qM, 16, h1f);
        logits_sample<<<B_ / 16, 256>>>(h1f, woutt, b_out, out, tok, t);
        p ^= 1;
    }
}